// round 2
// baseline (speedup 1.0000x reference)
#include <cuda_runtime.h>
#include <cstdint>

// Submanifold sparse conv: rulebook gather -> per-offset 16x16 GEMV -> scatter-add.
// Warp-cooperative layout: 4 lanes per rule (lane = rule*4 + quad), so gather and
// scatter-RED coalesce 4 lanes into one 64B row -> 4x fewer L1tex wavefronts.

constexpr int KOFF = 27;
constexpr int CIN  = 16;
constexpr int COUT = 16;

__global__ void init_bias_kernel(float4* __restrict__ out4,
                                 const float4* __restrict__ bias4,
                                 int n4 /* N*4 */) {
    int i = blockIdx.x * blockDim.x + threadIdx.x;
    if (i < n4) {
        out4[i] = bias4[i & 3];
    }
}

__device__ __forceinline__ float4 shfl_xor_f4(float4 v, int mask) {
    float4 r;
    r.x = __shfl_xor_sync(0xffffffffu, v.x, mask);
    r.y = __shfl_xor_sync(0xffffffffu, v.y, mask);
    r.z = __shfl_xor_sync(0xffffffffu, v.z, mask);
    r.w = __shfl_xor_sync(0xffffffffu, v.w, mask);
    return r;
}

__global__ void __launch_bounds__(256)
subconv_kernel(const float4* __restrict__ feat4,    // [N*4] (N rows x 16 f32)
               const float4* __restrict__ weight4,  // [27*64] ([k][c][qcol])
               const int*    __restrict__ rin,      // [27*R]
               const int*    __restrict__ rout,     // [27*R]
               float*        __restrict__ out,      // [N*16]
               int R) {
    // Weight tile for this offset: wsh[c*4 + qcol] = W[c][4*qcol .. 4*qcol+3]
    __shared__ float4 wsh[CIN * 4];

    const int k = blockIdx.y;
    if (threadIdx.x < CIN * 4) {
        wsh[threadIdx.x] = weight4[k * CIN * 4 + threadIdx.x];
    }
    __syncthreads();

    const int lane = threadIdx.x & 31;
    const int warp = threadIdx.x >> 5;
    const int q    = lane & 3;    // quad-lane: owns channels/outputs [4q, 4q+4)
    const int rs   = lane >> 2;   // rule slot within warp (8 rules per warp-iter)
    const long kbase = (long)k * R;

    // 8 warps/block, 8 rules/warp/iter = 64 rules per block-iter.
    for (int r0 = blockIdx.x * 64 + warp * 8; r0 < R; r0 += gridDim.x * 64) {
        const int  r     = r0 + rs;
        const bool valid = (r < R);
        const int  idx   = valid ? r : 0;

        const int ii = rin[kbase + idx];
        const int io = rout[kbase + idx];

        // Gather: 4 lanes of a quad each load one float4 of the same 64B row
        // -> one 128B line per rule, coalesced.
        const float4 v0 = feat4[(long)ii * 4 + q];

        // Exchange quads within the 4-lane group: lane ends up holding the
        // feature quad of lane^1, lane^2, lane^3 (i.e. channel groups q^1,q^2,q^3).
        const float4 f1 = shfl_xor_f4(v0, 1);
        const float4 f2 = shfl_xor_f4(v0, 2);
        const float4 f3 = shfl_xor_f4(f1, 2);   // = v0 of lane^3

        float4 acc = make_float4(0.f, 0.f, 0.f, 0.f);

        // Group g contributes channels c = 4*(q^g) + {0..3}; this lane computes
        // output quad [4q, 4q+4), so it needs weight rows c, column block q.
#pragma unroll
        for (int g = 0; g < 4; ++g) {
            const int qq = q ^ g;
            float4 fg;
            if      (g == 0) fg = v0;
            else if (g == 1) fg = f1;
            else if (g == 2) fg = f2;
            else             fg = f3;

            const float4 w0 = wsh[(qq * 4 + 0) * 4 + q];
            const float4 w1 = wsh[(qq * 4 + 1) * 4 + q];
            const float4 w2 = wsh[(qq * 4 + 2) * 4 + q];
            const float4 w3 = wsh[(qq * 4 + 3) * 4 + q];

            acc.x += fg.x * w0.x; acc.y += fg.x * w0.y; acc.z += fg.x * w0.z; acc.w += fg.x * w0.w;
            acc.x += fg.y * w1.x; acc.y += fg.y * w1.y; acc.z += fg.y * w1.z; acc.w += fg.y * w1.w;
            acc.x += fg.z * w2.x; acc.y += fg.z * w2.y; acc.z += fg.z * w2.z; acc.w += fg.z * w2.w;
            acc.x += fg.w * w3.x; acc.y += fg.w * w3.y; acc.z += fg.w * w3.z; acc.w += fg.w * w3.w;
        }

        // Scatter: 4 lanes of the quad RED into the same 64B output row
        // -> one line-wavefront per rule.
        if (valid) {
            float* op = out + (long)io * COUT + q * 4;
            asm volatile("red.global.add.v4.f32 [%0], {%1,%2,%3,%4};"
                         :: "l"(op), "f"(acc.x), "f"(acc.y), "f"(acc.z), "f"(acc.w)
                         : "memory");
        }
    }
}

extern "C" void kernel_launch(void* const* d_in, const int* in_sizes, int n_in,
                              void* d_out, int out_size) {
    const float* features = (const float*)d_in[0];   // [N*16]
    const float* weight   = (const float*)d_in[1];   // [27*16*16]
    const float* bias     = (const float*)d_in[2];   // [16]
    const int*   rules_in = (const int*)d_in[3];     // [27*R]
    const int*   rules_out= (const int*)d_in[4];     // [27*R]
    float* out = (float*)d_out;                      // [N*16]

    const int N = in_sizes[0] / CIN;
    const int R = in_sizes[3] / KOFF;
    const int n4 = N * 4;

    // 1) out = bias broadcast (vectorized)
    {
        const int threads = 256;
        const int blocks = (n4 + threads - 1) / threads;
        init_bias_kernel<<<blocks, threads>>>(
            (float4*)out, (const float4*)bias, n4);
    }

    // 2) gather -> GEMV -> scatter-add, 4 iterations per warp
    {
        const int threads = 256;
        const int rules_per_block_pass = 256;  // 64 per iter * 4 iters
        dim3 grid((R + rules_per_block_pass - 1) / rules_per_block_pass, KOFF);
        subconv_kernel<<<grid, threads>>>(
            reinterpret_cast<const float4*>(features),
            reinterpret_cast<const float4*>(weight),
            rules_in, rules_out, out, R);
    }
}

// round 3
// speedup vs baseline: 1.0243x; 1.0243x over previous
#include <cuda_runtime.h>
#include <cstdint>

// Submanifold sparse conv: rulebook gather -> per-offset 16x16 GEMV -> scatter-add.
// Quad-cooperative (4 lanes per rule) for 1-wavefront gather + 1-wavefront RED,
// with U=4 rule batching for MLP and a partial-sum butterfly that keeps shuffles
// off the load->FMA critical path.

constexpr int KOFF = 27;
constexpr int CIN  = 16;
constexpr int COUT = 16;
constexpr int U    = 4;    // rules per lane-slot
constexpr int WPAD = 17;   // float4 stride per weight replica (16 + 1 pad)

__global__ void init_bias_kernel(float4* __restrict__ out4,
                                 const float4* __restrict__ bias4,
                                 int n4 /* N*4 */) {
    int i = blockIdx.x * blockDim.x + threadIdx.x;
    if (i < n4) {
        out4[i] = bias4[i & 3];
    }
}

__device__ __forceinline__ float4 shfl_xor_f4(float4 v, int mask) {
    float4 r;
    r.x = __shfl_xor_sync(0xffffffffu, v.x, mask);
    r.y = __shfl_xor_sync(0xffffffffu, v.y, mask);
    r.z = __shfl_xor_sync(0xffffffffu, v.z, mask);
    r.w = __shfl_xor_sync(0xffffffffu, v.w, mask);
    return r;
}

__device__ __forceinline__ float4 f4add(float4 a, float4 b) {
    return make_float4(a.x + b.x, a.y + b.y, a.z + b.z, a.w + b.w);
}

__global__ void __launch_bounds__(256)
subconv_kernel(const float4* __restrict__ feat4,    // [N*4]
               const float4* __restrict__ weight4,  // [27*64]
               const int*    __restrict__ rin,      // [27*R]
               const int*    __restrict__ rout,     // [27*R]
               float*        __restrict__ out,      // [N*16]
               int R) {
    // Per-quad weight partition, bank-padded: replica q holds W[4q+c][4j..4j+3]
    // at wsh[q*WPAD + c*4 + j]. Global float4 layout is [k*64 + cin*4 + j], so
    // replica q's 16 entries are exactly weight4[k*64 + q*16 .. +15] (contiguous).
    __shared__ float4 wsh[4 * WPAD];

    const int k = blockIdx.y;
    if (threadIdx.x < 64) {
        const int q  = threadIdx.x >> 4;
        const int cj = threadIdx.x & 15;
        wsh[q * WPAD + cj] = weight4[k * 64 + threadIdx.x];
    }
    __syncthreads();

    const int lane = threadIdx.x & 31;
    const int warp = threadIdx.x >> 5;
    const int q    = lane & 3;    // channel/output quad owned by this lane
    const int rs   = lane >> 2;   // rule slot (8 per warp per u)
    const long kbase = (long)k * R;
    const int rbase = blockIdx.x * 256 + warp * 32 + rs;

    // ---- phase 1: all index loads (independent, in flight together) ----
    int  ii[U], io[U];
    bool valid[U];
#pragma unroll
    for (int u = 0; u < U; ++u) {
        const int r = rbase + u * 8;
        valid[u] = (r < R);
        const int idx = valid[u] ? r : 0;
        ii[u] = rin[kbase + idx];
        io[u] = rout[kbase + idx];
    }

    // ---- phase 2: all gathers (MLP=4; 4 lanes coalesce into one 64B row) ----
    float4 g[U];
#pragma unroll
    for (int u = 0; u < U; ++u) {
        g[u] = feat4[(long)ii[u] * 4 + q];
    }

    const float4* wq = &wsh[q * WPAD];
    const bool hi  = (q & 2) != 0;
    const bool odd = (q & 1) != 0;

    // ---- phase 3: per rule: FMA -> butterfly reduce -> RED ----
#pragma unroll
    for (int u = 0; u < U; ++u) {
        const float4 f = g[u];
        const float fc[4] = {f.x, f.y, f.z, f.w};

        // P[j] = contribution of channels [4q,4q+4) to outputs [4j,4j+4)
        float4 P0 = make_float4(0.f, 0.f, 0.f, 0.f);
        float4 P1 = P0, P2 = P0, P3 = P0;
#pragma unroll
        for (int c = 0; c < 4; ++c) {
            const float  s  = fc[c];
            const float4 w0 = wq[c * 4 + 0];
            const float4 w1 = wq[c * 4 + 1];
            const float4 w2 = wq[c * 4 + 2];
            const float4 w3 = wq[c * 4 + 3];
            P0.x += s * w0.x; P0.y += s * w0.y; P0.z += s * w0.z; P0.w += s * w0.w;
            P1.x += s * w1.x; P1.y += s * w1.y; P1.z += s * w1.z; P1.w += s * w1.w;
            P2.x += s * w2.x; P2.y += s * w2.y; P2.z += s * w2.z; P2.w += s * w2.w;
            P3.x += s * w3.x; P3.y += s * w3.y; P3.z += s * w3.z; P3.w += s * w3.w;
        }

        // Butterfly stage 1 (xor 2): keep the two output-quads in our pair
        // group {2*(q>>1), 2*(q>>1)+1}, send the other two.
        const float4 keepA = hi ? P2 : P0;
        const float4 keepB = hi ? P3 : P1;
        const float4 sendA = hi ? P0 : P2;
        const float4 sendB = hi ? P1 : P3;
        const float4 TA = f4add(keepA, shfl_xor_f4(sendA, 2)); // quad 2*(q>>1)
        const float4 TB = f4add(keepB, shfl_xor_f4(sendB, 2)); // quad 2*(q>>1)+1

        // Butterfly stage 2 (xor 1): end with the full sum for output quad q.
        const float4 keep = odd ? TB : TA;
        const float4 send = odd ? TA : TB;
        const float4 S = f4add(keep, shfl_xor_f4(send, 1));

        if (valid[u]) {
            float* op = out + (long)io[u] * COUT + q * 4;
            asm volatile("red.global.add.v4.f32 [%0], {%1,%2,%3,%4};"
                         :: "l"(op), "f"(S.x), "f"(S.y), "f"(S.z), "f"(S.w)
                         : "memory");
        }
    }
}

extern "C" void kernel_launch(void* const* d_in, const int* in_sizes, int n_in,
                              void* d_out, int out_size) {
    const float* features = (const float*)d_in[0];   // [N*16]
    const float* weight   = (const float*)d_in[1];   // [27*16*16]
    const float* bias     = (const float*)d_in[2];   // [16]
    const int*   rules_in = (const int*)d_in[3];     // [27*R]
    const int*   rules_out= (const int*)d_in[4];     // [27*R]
    float* out = (float*)d_out;                      // [N*16]

    const int N = in_sizes[0] / CIN;
    const int R = in_sizes[3] / KOFF;
    const int n4 = N * 4;

    // 1) out = bias broadcast (vectorized)
    {
        const int threads = 256;
        const int blocks = (n4 + threads - 1) / threads;
        init_bias_kernel<<<blocks, threads>>>(
            (float4*)out, (const float4*)bias, n4);
    }

    // 2) gather -> GEMV -> scatter-add; 256 rules per block, no block loop
    {
        const int threads = 256;
        dim3 grid((R + 255) / 256, KOFF);
        subconv_kernel<<<grid, threads>>>(
            reinterpret_cast<const float4*>(features),
            reinterpret_cast<const float4*>(weight),
            rules_in, rules_out, out, R);
    }
}

// round 4
// speedup vs baseline: 1.7773x; 1.7352x over previous
#include <cuda_runtime.h>
#include <cstdint>

// Submanifold sparse conv: rulebook gather -> per-offset 16x16 GEMV -> scatter-add.
// Quad-cooperative (4 lanes per rule): coalesced 64B gather + coalesced RED.
// U=4 rule batching for gather MLP; g-outer loop shares weight LDS across rules;
// single-hop feature shuffles; 4-float accumulator per rule to keep regs low.

constexpr int KOFF = 27;
constexpr int CIN  = 16;
constexpr int COUT = 16;
constexpr int U    = 4;    // rules per lane-slot

__global__ void init_bias_kernel(float4* __restrict__ out4,
                                 const float4* __restrict__ bias4,
                                 int n4 /* N*4 */) {
    int i = blockIdx.x * blockDim.x + threadIdx.x;
    if (i < n4) {
        out4[i] = bias4[i & 3];
    }
}

__device__ __forceinline__ float4 shfl_xor_f4(float4 v, int mask) {
    float4 r;
    r.x = __shfl_xor_sync(0xffffffffu, v.x, mask);
    r.y = __shfl_xor_sync(0xffffffffu, v.y, mask);
    r.z = __shfl_xor_sync(0xffffffffu, v.z, mask);
    r.w = __shfl_xor_sync(0xffffffffu, v.w, mask);
    return r;
}

__global__ void __launch_bounds__(256, 3)
subconv_kernel(const float4* __restrict__ feat4,    // [N*4]
               const float4* __restrict__ weight4,  // [27*64] : [k][cin][j] j=out quad
               const int*    __restrict__ rin,      // [27*R]
               const int*    __restrict__ rout,     // [27*R]
               float*        __restrict__ out,      // [N*16]
               int R) {
    // wsh[c*4 + j] = W[c][4j..4j+3] for this offset k
    __shared__ float4 wsh[CIN * 4];

    const int k = blockIdx.y;
    if (threadIdx.x < CIN * 4) {
        wsh[threadIdx.x] = weight4[k * (CIN * 4) + threadIdx.x];
    }
    __syncthreads();

    const int lane = threadIdx.x & 31;
    const int warp = threadIdx.x >> 5;
    const int q    = lane & 3;    // this lane owns feature quad q and output quad q
    const int rs   = lane >> 2;   // rule slot (8 per warp)
    const long kbase = (long)k * R;
    const int rbase = blockIdx.x * 256 + warp * 32 + rs;

    // ---- phase 1: all index loads in flight together ----
    int  ii[U], io[U];
    bool valid[U];
#pragma unroll
    for (int u = 0; u < U; ++u) {
        const int r = rbase + u * 8;
        valid[u] = (r < R);
        const int idx = valid[u] ? r : 0;
        ii[u] = rin[kbase + idx];
        io[u] = rout[kbase + idx];
    }

    // ---- phase 2: all gathers (MLP=4; quad lanes coalesce into one 64B row) ----
    float4 v[U];
#pragma unroll
    for (int u = 0; u < U; ++u) {
        v[u] = feat4[(long)ii[u] * 4 + q];
    }

    float4 acc[U];
#pragma unroll
    for (int u = 0; u < U; ++u) acc[u] = make_float4(0.f, 0.f, 0.f, 0.f);

    // ---- phase 3: g outer (share weight loads across rules), u inner ----
#pragma unroll
    for (int g = 0; g < 4; ++g) {
        const int qq = q ^ g;   // channel group applied this step
        // Weight rows 4qq..4qq+3, output-quad column q. 4 distinct 16B
        // addresses across the warp -> conflict-free broadcast.
        const float4 w0 = wsh[(qq * 4 + 0) * 4 + q];
        const float4 w1 = wsh[(qq * 4 + 1) * 4 + q];
        const float4 w2 = wsh[(qq * 4 + 2) * 4 + q];
        const float4 w3 = wsh[(qq * 4 + 3) * 4 + q];

#pragma unroll
        for (int u = 0; u < U; ++u) {
            // Feature quad qq of rule u lives in lane^g (single-hop shuffle).
            const float4 fg = (g == 0) ? v[u] : shfl_xor_f4(v[u], g);
            acc[u].x += fg.x * w0.x; acc[u].y += fg.x * w0.y;
            acc[u].z += fg.x * w0.z; acc[u].w += fg.x * w0.w;
            acc[u].x += fg.y * w1.x; acc[u].y += fg.y * w1.y;
            acc[u].z += fg.y * w1.z; acc[u].w += fg.y * w1.w;
            acc[u].x += fg.z * w2.x; acc[u].y += fg.z * w2.y;
            acc[u].z += fg.z * w2.z; acc[u].w += fg.z * w2.w;
            acc[u].x += fg.w * w3.x; acc[u].y += fg.w * w3.y;
            acc[u].z += fg.w * w3.z; acc[u].w += fg.w * w3.w;
        }
    }

    // ---- phase 4: coalesced scatter-RED (quad lanes hit one 64B row) ----
#pragma unroll
    for (int u = 0; u < U; ++u) {
        if (valid[u]) {
            float* op = out + (long)io[u] * COUT + q * 4;
            asm volatile("red.global.add.v4.f32 [%0], {%1,%2,%3,%4};"
                         :: "l"(op),
                            "f"(acc[u].x), "f"(acc[u].y),
                            "f"(acc[u].z), "f"(acc[u].w)
                         : "memory");
        }
    }
}

extern "C" void kernel_launch(void* const* d_in, const int* in_sizes, int n_in,
                              void* d_out, int out_size) {
    const float* features = (const float*)d_in[0];   // [N*16]
    const float* weight   = (const float*)d_in[1];   // [27*16*16]
    const float* bias     = (const float*)d_in[2];   // [16]
    const int*   rules_in = (const int*)d_in[3];     // [27*R]
    const int*   rules_out= (const int*)d_in[4];     // [27*R]
    float* out = (float*)d_out;                      // [N*16]

    const int N = in_sizes[0] / CIN;
    const int R = in_sizes[3] / KOFF;
    const int n4 = N * 4;

    // 1) out = bias broadcast (vectorized)
    {
        const int threads = 256;
        const int blocks = (n4 + threads - 1) / threads;
        init_bias_kernel<<<blocks, threads>>>(
            (float4*)out, (const float4*)bias, n4);
    }

    // 2) gather -> GEMV -> scatter-add; 256 rules per block
    {
        const int threads = 256;
        dim3 grid((R + 255) / 256, KOFF);
        subconv_kernel<<<grid, threads>>>(
            reinterpret_cast<const float4*>(features),
            reinterpret_cast<const float4*>(weight),
            rules_in, rules_out, out, R);
    }
}